// round 1
// baseline (speedup 1.0000x reference)
#include <cuda_runtime.h>
#include <cstdint>

#define B_ 64
#define Q_ 900
#define T_ 100
#define C_ 256
#define NT 256

// Scratch: transposed cost [B, T, Q] so hungarian reads contiguous rows.
__device__ float g_costT[(size_t)B_ * T_ * Q_];

// ---------------------------------------------------------------------------
// Kernel 1: cost matrix [B,Q,T] -> d_out (first B*Q*T floats)
// ---------------------------------------------------------------------------
__global__ void cost_kernel(const float* __restrict__ logits,
                            const float* __restrict__ pboxes,
                            const int* __restrict__ labels,
                            const float* __restrict__ tboxes,
                            float* __restrict__ cost) {
    long long idx = (long long)blockIdx.x * blockDim.x + threadIdx.x;
    if (idx >= (long long)B_ * Q_ * T_) return;
    int t = (int)(idx % T_);
    long long bq = idx / T_;
    int q = (int)(bq % Q_);
    int b = (int)(bq / Q_);

    int lab = labels[b * T_ + t];
    float cc = -__ldg(&logits[((long long)b * Q_ + q) * C_ + lab]);

    float4 pb = __ldg(&((const float4*)pboxes)[b * Q_ + q]);
    float4 tb = __ldg(&((const float4*)tboxes)[b * T_ + t]);

    // L1 (cxcywh), same summation order as reference
    float cb = fabsf(pb.x - tb.x) + fabsf(pb.y - tb.y);
    cb += fabsf(pb.z - tb.z);
    cb += fabsf(pb.w - tb.w);

    // xyxy
    float ax0 = pb.x - 0.5f * pb.z, ay0 = pb.y - 0.5f * pb.w;
    float ax1 = pb.x + 0.5f * pb.z, ay1 = pb.y + 0.5f * pb.w;
    float bx0 = tb.x - 0.5f * tb.z, by0 = tb.y - 0.5f * tb.w;
    float bx1 = tb.x + 0.5f * tb.z, by1 = tb.y + 0.5f * tb.w;

    float areaA = (ax1 - ax0) * (ay1 - ay0);
    float areaB = (bx1 - bx0) * (by1 - by0);
    float wx = fminf(ax1, bx1) - fmaxf(ax0, bx0); wx = fmaxf(wx, 0.f);
    float wy = fminf(ay1, by1) - fmaxf(ay0, by0); wy = fmaxf(wy, 0.f);
    float inter = wx * wy;
    float uni = areaA + areaB - inter;
    float iou = inter / uni;
    float ex = fmaxf(ax1, bx1) - fminf(ax0, bx0); ex = fmaxf(ex, 0.f);
    float ey = fmaxf(ay1, by1) - fminf(ay0, by0); ey = fmaxf(ey, 0.f);
    float enc = ex * ey;
    float giou = iou - (enc - uni) / enc;

    cost[idx] = (cc + cb) - giou;
}

// ---------------------------------------------------------------------------
// Kernel 2: transpose [B,Q,T] -> [B,T,Q] (coalesced via smem tiles)
// ---------------------------------------------------------------------------
__global__ void transpose_kernel(const float* __restrict__ cost) {
    __shared__ float tile[32][33];
    int b = blockIdx.z;
    int q0 = blockIdx.x * 32, t0 = blockIdx.y * 32;
    int q = q0 + threadIdx.y, t = t0 + threadIdx.x;
    if (q < Q_ && t < T_)
        tile[threadIdx.y][threadIdx.x] = cost[((size_t)b * Q_ + q) * T_ + t];
    __syncthreads();
    int oq = q0 + threadIdx.x, ot = t0 + threadIdx.y;
    if (oq < Q_ && ot < T_)
        g_costT[((size_t)b * T_ + ot) * Q_ + oq] = tile[threadIdx.x][threadIdx.y];
}

// ---------------------------------------------------------------------------
// Kernel 3: Jonker-Volgenant shortest augmenting path. One CTA per batch.
// Mirrors the reference scan/while exactly (incl. virtual column Q_ and
// lowest-index argmin tie-breaking via packed 64-bit keys).
// ---------------------------------------------------------------------------
__global__ void __launch_bounds__(NT) hungarian_kernel(float* __restrict__ out,
                                                       int writeIdx) {
    int b = blockIdx.x;
    const float* cost = g_costT + (size_t)b * T_ * Q_;

    __shared__ float v[Q_];
    __shared__ float minv[Q_];
    __shared__ int way[Q_];
    __shared__ unsigned char used[Q_];
    __shared__ float u[T_ + 1];
    __shared__ int p[Q_ + 1];
    __shared__ int j0s;
    __shared__ unsigned long long wred[NT / 32];
    __shared__ int colarr[T_];

    int tid = threadIdx.x;

    for (int j = tid; j < Q_; j += NT) { v[j] = 0.f; p[j] = -1; way[j] = Q_; }
    for (int r = tid; r <= T_; r += NT) u[r] = 0.f;
    __syncthreads();

    for (int i = 0; i < T_; i++) {
        for (int j = tid; j < Q_; j += NT) { minv[j] = 1e9f; used[j] = 0; }
        if (tid == 0) { p[Q_] = i; j0s = Q_; }
        __syncthreads();

        int j1 = 0;
        while (true) {
            int j0 = j0s;
            int i0 = p[j0];            // guaranteed >= 0 here
            float ui0 = u[i0];
            const float* row = cost + (size_t)i0 * Q_;

            unsigned long long best = ~0ull;
            for (int j = tid; j < Q_; j += NT) {
                bool us = used[j] || (j == j0);
                if (!us) {
                    float cur = row[j] - ui0 - v[j];
                    float mv = minv[j];
                    if (cur < mv) { mv = cur; minv[j] = cur; way[j] = j0; }
                    unsigned int o = __float_as_uint(mv);
                    o = (o & 0x80000000u) ? ~o : (o | 0x80000000u);
                    unsigned long long key = ((unsigned long long)o << 32) | (unsigned int)j;
                    if (key < best) best = key;
                } else if (j == j0) {
                    used[j] = 1;       // mark for future iterations
                }
            }
            // warp-level min reduce (64-bit packed key)
            #pragma unroll
            for (int off = 16; off; off >>= 1) {
                unsigned long long oth = __shfl_down_sync(0xFFFFFFFFu, best, off);
                if (oth < best) best = oth;
            }
            if ((tid & 31) == 0) wred[tid >> 5] = best;
            __syncthreads();

            unsigned long long tot = wred[0];
            #pragma unroll
            for (int w = 1; w < NT / 32; w++)
                if (wred[w] < tot) tot = wred[w];
            j1 = (int)(tot & 0xFFFFFFFFu);
            unsigned int o = (unsigned int)(tot >> 32);
            float delta = __uint_as_float((o & 0x80000000u) ? (o ^ 0x80000000u) : ~o);

            // dual / slack updates (reference semantics)
            for (int j = tid; j < Q_; j += NT) {
                if (used[j]) { v[j] -= delta; u[p[j]] += delta; }
                else         { minv[j] -= delta; }
            }
            if (tid == 0) {
                u[i] += delta;         // virtual column Q_ (p[Q_] = i, always used)
                j0s = j1;
            }
            __syncthreads();
            if (p[j1] < 0) break;      // free column found
        }

        // augment along predecessor chain
        if (tid == 0) {
            int j = j1;
            while (j != Q_) { int jn = way[j]; p[j] = p[jn]; j = jn; }
        }
        __syncthreads();
    }

    // col[t] = query matched to target t; then sort (ranks via counting, T=100)
    for (int j = tid; j < Q_; j += NT) {
        int r = p[j];
        if (r >= 0) colarr[r] = j;
    }
    __syncthreads();

    if (writeIdx) {
        float* oidx = out + (size_t)B_ * Q_ * T_;
        for (int t = tid; t < T_; t += NT) {
            int c = colarr[t];
            int rank = 0;
            for (int s = 0; s < T_; s++) rank += (colarr[s] < c);
            oidx[(size_t)b * T_ + rank] = (float)c;                       // pred_idx
            oidx[(size_t)B_ * T_ + (size_t)b * T_ + rank] = (float)t;     // tgt_idx
        }
    }
}

// ---------------------------------------------------------------------------
extern "C" void kernel_launch(void* const* d_in, const int* in_sizes, int n_in,
                              void* d_out, int out_size) {
    const float* logits = (const float*)d_in[0];
    const float* pboxes = (const float*)d_in[1];
    const int*   labels = (const int*)d_in[2];
    const float* tboxes = (const float*)d_in[3];
    float* out = (float*)d_out;

    long long n = (long long)B_ * Q_ * T_;
    cost_kernel<<<(unsigned)((n + 255) / 256), 256>>>(logits, pboxes, labels, tboxes, out);

    dim3 tb(32, 32);
    dim3 tg((Q_ + 31) / 32, (T_ + 31) / 32, B_);
    transpose_kernel<<<tg, tb>>>(out);

    int writeIdx = (out_size >= (int)((long long)B_ * Q_ * T_ + 2LL * B_ * T_)) ? 1 : 0;
    hungarian_kernel<<<B_, NT>>>(out, writeIdx);
}

// round 2
// speedup vs baseline: 1.0215x; 1.0215x over previous
#include <cuda_runtime.h>
#include <cstdint>

#define B_ 64
#define Q_ 900
#define T_ 100
#define C_ 256
#define NT 256
#define K_ 4            // columns per thread: NT*K_ >= Q_
#define NW (NT / 32)

// Scratch: transposed cost [B, T, Q] so hungarian reads contiguous rows.
__device__ float g_costT[(size_t)B_ * T_ * Q_];

// ---------------------------------------------------------------------------
// Kernel 1 (fused): cost matrix -> d_out [B,Q,T]  AND  g_costT [B,T,Q]
// ---------------------------------------------------------------------------
__global__ void cost_fused_kernel(const float* __restrict__ logits,
                                  const float* __restrict__ pboxes,
                                  const int* __restrict__ labels,
                                  const float* __restrict__ tboxes,
                                  float* __restrict__ cost) {
    __shared__ float tile[32][33];
    int b = blockIdx.z;
    int q0 = blockIdx.x * 32, t0 = blockIdx.y * 32;
    int q = q0 + threadIdx.y;
    int t = t0 + threadIdx.x;

    float val = 0.f;
    if (q < Q_ && t < T_) {
        int lab = labels[b * T_ + t];
        float cc = -__ldg(&logits[((long long)b * Q_ + q) * C_ + lab]);

        float4 pb = __ldg(&((const float4*)pboxes)[b * Q_ + q]);
        float4 tb = __ldg(&((const float4*)tboxes)[b * T_ + t]);

        float cb = fabsf(pb.x - tb.x) + fabsf(pb.y - tb.y);
        cb += fabsf(pb.z - tb.z);
        cb += fabsf(pb.w - tb.w);

        float ax0 = pb.x - 0.5f * pb.z, ay0 = pb.y - 0.5f * pb.w;
        float ax1 = pb.x + 0.5f * pb.z, ay1 = pb.y + 0.5f * pb.w;
        float bx0 = tb.x - 0.5f * tb.z, by0 = tb.y - 0.5f * tb.w;
        float bx1 = tb.x + 0.5f * tb.z, by1 = tb.y + 0.5f * tb.w;

        float areaA = (ax1 - ax0) * (ay1 - ay0);
        float areaB = (bx1 - bx0) * (by1 - by0);
        float wx = fminf(ax1, bx1) - fmaxf(ax0, bx0); wx = fmaxf(wx, 0.f);
        float wy = fminf(ay1, by1) - fmaxf(ay0, by0); wy = fmaxf(wy, 0.f);
        float inter = wx * wy;
        float uni = areaA + areaB - inter;
        float iou = inter / uni;
        float ex = fmaxf(ax1, bx1) - fminf(ax0, bx0); ex = fmaxf(ex, 0.f);
        float ey = fmaxf(ay1, by1) - fminf(ay0, by0); ey = fmaxf(ey, 0.f);
        float enc = ex * ey;
        float giou = iou - (enc - uni) / enc;

        val = (cc + cb) - giou;
        cost[((size_t)b * Q_ + q) * T_ + t] = val;
    }
    tile[threadIdx.y][threadIdx.x] = val;
    __syncthreads();
    int oq = q0 + threadIdx.x, ot = t0 + threadIdx.y;
    if (oq < Q_ && ot < T_)
        g_costT[((size_t)b * T_ + ot) * Q_ + oq] = tile[threadIdx.x][threadIdx.y];
}

// ---------------------------------------------------------------------------
// Kernel 2: JV shortest augmenting path, deferred dual updates,
// register-resident column state, 1 barrier per inner iteration.
// One CTA per batch. Matches reference semantics incl. lowest-index argmin.
// ---------------------------------------------------------------------------
__global__ void __launch_bounds__(NT) hungarian_kernel(float* __restrict__ out,
                                                       int writeIdx) {
    int b = blockIdx.x;
    const float* cost = g_costT + (size_t)b * T_ * Q_;

    __shared__ float u[T_ + 1];
    __shared__ int p[Q_];                 // row matched to col j (-1 free)
    __shared__ int sway[Q_];              // predecessor column
    __shared__ unsigned long long wred[2][NW];
    __shared__ int colarr[T_];

    int tid = threadIdx.x;
    int lane = tid & 31, wid = tid >> 5;

    float vreg[K_];                       // column dual, register-resident
    float minv[K_];                       // absolute shortest-path dist
    #pragma unroll
    for (int k = 0; k < K_; k++) vreg[k] = 0.f;

    for (int j = tid; j < Q_; j += NT) p[j] = -1;
    for (int r = tid; r <= T_; r += NT) u[r] = 0.f;
    __syncthreads();

    for (int i = 0; i < T_; i++) {
        unsigned um = 0;                  // used bitmask for my K_ columns
        #pragma unroll
        for (int k = 0; k < K_; k++) {
            minv[k] = 1e30f;
            if (tid + k * NT >= Q_) um |= (1u << k);   // tail cols: never free
        }

        int j0 = Q_;                      // virtual start column
        int i0 = i;
        float shift = 0.f;                // dist(j0)
        int iter = 0;
        int j1;
        float Sf;

        while (true) {
            float base = shift - u[i0];
            const float* row = cost + (size_t)i0 * Q_;

            unsigned long long best = ~0ull;
            #pragma unroll
            for (int k = 0; k < K_; k++) {
                int j = tid + k * NT;
                if (!((um >> k) & 1u)) {
                    float cur = __ldg(row + j) - vreg[k] + base;
                    if (cur < minv[k]) { minv[k] = cur; sway[j] = j0; }
                    unsigned int o = __float_as_uint(minv[k]);
                    o = (o & 0x80000000u) ? ~o : (o | 0x80000000u);
                    unsigned long long key =
                        ((unsigned long long)o << 32) | (unsigned)j;
                    if (key < best) best = key;
                }
            }
            #pragma unroll
            for (int off = 16; off; off >>= 1) {
                unsigned long long oth = __shfl_xor_sync(0xFFFFFFFFu, best, off);
                if (oth < best) best = oth;
            }
            int buf = iter & 1;
            if (lane == 0) wred[buf][wid] = best;
            __syncthreads();

            unsigned long long tot = wred[buf][0];
            #pragma unroll
            for (int w = 1; w < NW; w++)
                if (wred[buf][w] < tot) tot = wred[buf][w];
            j1 = (int)(tot & 0xFFFFFFFFu);
            unsigned int o = (unsigned int)(tot >> 32);
            Sf = __uint_as_float((o & 0x80000000u) ? (o ^ 0x80000000u) : ~o);

            int i0n = p[j1];
            if (i0n < 0) break;           // free column -> augment

            // continue: j1 enters the tree (its owner freezes minv = dist)
            if ((j1 % NT) == tid) um |= (1u << (j1 / NT));
            j0 = j1;
            i0 = i0n;
            shift = Sf;
            iter++;
        }

        // deferred dual updates (exactly what the in-loop updates sum to)
        #pragma unroll
        for (int k = 0; k < K_; k++) {
            int j = tid + k * NT;
            if (j < Q_ && ((um >> k) & 1u)) {
                float diff = Sf - minv[k];   // S_final - dist(j)
                vreg[k] -= diff;
                u[p[j]] += diff;             // rows distinct across used cols
            }
        }
        if (tid == 0) u[i] += Sf;
        __syncthreads();                     // duals read p before augment writes

        if (tid == 0) {
            int j = j1;
            while (j != Q_) {
                int jn = sway[j];
                p[j] = (jn == Q_) ? i : p[jn];
                j = jn;
            }
        }
        __syncthreads();
    }

    // col[t] = matched query; write indices sorted by query (rank via count)
    for (int j = tid; j < Q_; j += NT) {
        int r = p[j];
        if (r >= 0) colarr[r] = j;
    }
    __syncthreads();

    if (writeIdx) {
        float* oidx = out + (size_t)B_ * Q_ * T_;
        for (int t = tid; t < T_; t += NT) {
            int c = colarr[t];
            int rank = 0;
            for (int s = 0; s < T_; s++) rank += (colarr[s] < c);
            oidx[(size_t)b * T_ + rank] = (float)c;                    // pred_idx
            oidx[(size_t)B_ * T_ + (size_t)b * T_ + rank] = (float)t;  // tgt_idx
        }
    }
}

// ---------------------------------------------------------------------------
extern "C" void kernel_launch(void* const* d_in, const int* in_sizes, int n_in,
                              void* d_out, int out_size) {
    const float* logits = (const float*)d_in[0];
    const float* pboxes = (const float*)d_in[1];
    const int*   labels = (const int*)d_in[2];
    const float* tboxes = (const float*)d_in[3];
    float* out = (float*)d_out;

    dim3 tb(32, 32);
    dim3 tg((Q_ + 31) / 32, (T_ + 31) / 32, B_);
    cost_fused_kernel<<<tg, tb>>>(logits, pboxes, labels, tboxes, out);

    int writeIdx = (out_size >= (int)((long long)B_ * Q_ * T_ + 2LL * B_ * T_)) ? 1 : 0;
    hungarian_kernel<<<B_, NT>>>(out, writeIdx);
}

// round 3
// speedup vs baseline: 2.9599x; 2.8976x over previous
#include <cuda_runtime.h>
#include <cstdint>

#define B_ 64
#define Q_ 900
#define T_ 100
#define C_ 256
#define NT 256
#define K_ 4            // columns per thread: NT*K_ >= Q_
#define NW (NT / 32)

// Scratch: transposed cost [B, T, Q] so hungarian reads contiguous rows.
__device__ float g_costT[(size_t)B_ * T_ * Q_];

__device__ __forceinline__ unsigned order_f(float f) {
    unsigned o = __float_as_uint(f);
    return (o & 0x80000000u) ? ~o : (o | 0x80000000u);
}
__device__ __forceinline__ float unorder_f(unsigned o) {
    return __uint_as_float((o & 0x80000000u) ? (o ^ 0x80000000u) : ~o);
}

// ---------------------------------------------------------------------------
// Kernel 1: one block per (b, 32-query tile). Computes cost for all T targets,
// writes out[B,Q,T] coalesced and g_costT[B,T,Q] coalesced via smem tile.
// ---------------------------------------------------------------------------
__global__ void __launch_bounds__(NT) cost_fused_kernel(
        const float* __restrict__ logits,
        const float* __restrict__ pboxes,
        const int* __restrict__ labels,
        const float* __restrict__ tboxes,
        float* __restrict__ out) {
    __shared__ int   lab_s[T_];
    __shared__ float4 tb_s[T_];
    __shared__ float4 pb_s[32];
    __shared__ float tile[32][101];   // [q_in_tile][t], 101 coprime w/ 32

    int b = blockIdx.y;
    int q0 = blockIdx.x * 32;
    int tid = threadIdx.x;

    if (tid < T_) {
        lab_s[tid] = labels[b * T_ + tid];
        tb_s[tid] = __ldg(&((const float4*)tboxes)[b * T_ + tid]);
    }
    if (tid < 32 && q0 + tid < Q_)
        pb_s[tid] = __ldg(&((const float4*)pboxes)[b * Q_ + q0 + tid]);
    __syncthreads();

    for (int idx = tid; idx < 32 * T_; idx += NT) {
        int qq = idx / T_, tt = idx % T_;
        int q = q0 + qq;
        if (q >= Q_) break;

        float cc = -__ldg(&logits[((long long)b * Q_ + q) * C_ + lab_s[tt]]);
        float4 pb = pb_s[qq];
        float4 tb = tb_s[tt];

        float cb = fabsf(pb.x - tb.x) + fabsf(pb.y - tb.y);
        cb += fabsf(pb.z - tb.z);
        cb += fabsf(pb.w - tb.w);

        float ax0 = pb.x - 0.5f * pb.z, ay0 = pb.y - 0.5f * pb.w;
        float ax1 = pb.x + 0.5f * pb.z, ay1 = pb.y + 0.5f * pb.w;
        float bx0 = tb.x - 0.5f * tb.z, by0 = tb.y - 0.5f * tb.w;
        float bx1 = tb.x + 0.5f * tb.z, by1 = tb.y + 0.5f * tb.w;

        float areaA = (ax1 - ax0) * (ay1 - ay0);
        float areaB = (bx1 - bx0) * (by1 - by0);
        float wx = fminf(ax1, bx1) - fmaxf(ax0, bx0); wx = fmaxf(wx, 0.f);
        float wy = fminf(ay1, by1) - fmaxf(ay0, by0); wy = fmaxf(wy, 0.f);
        float inter = wx * wy;
        float uni = areaA + areaB - inter;
        float iou = inter / uni;
        float ex = fmaxf(ax1, bx1) - fminf(ax0, bx0); ex = fmaxf(ex, 0.f);
        float ey = fmaxf(ay1, by1) - fminf(ay0, by0); ey = fmaxf(ey, 0.f);
        float enc = ex * ey;
        float giou = iou - (enc - uni) / enc;

        float val = (cc + cb) - giou;
        tile[qq][tt] = val;
        out[((size_t)b * Q_ + q) * T_ + tt] = val;          // coalesced (t fast)
    }
    __syncthreads();

    for (int idx = tid; idx < 32 * T_; idx += NT) {
        int tt = idx / 32, qq = idx % 32;
        int q = q0 + qq;
        if (q < Q_)
            g_costT[((size_t)b * T_ + tt) * Q_ + q] = tile[qq][tt];  // coalesced (q fast)
    }
}

// ---------------------------------------------------------------------------
// Kernel 2: JV with greedy initialization + deferred-dual shortest augmenting
// path. One CTA per batch.
// ---------------------------------------------------------------------------
__global__ void __launch_bounds__(NT) hungarian_kernel(float* __restrict__ out,
                                                       int writeIdx) {
    int b = blockIdx.x;
    const float* cost = g_costT + (size_t)b * T_ * Q_;

    __shared__ float u[T_ + 1];
    __shared__ int p[Q_];                 // row matched to col j (-1 free)
    __shared__ int sway[Q_];              // predecessor column
    __shared__ unsigned long long wred[2][NW];
    __shared__ int colarr[T_];
    __shared__ int argj[T_];
    __shared__ int matched[T_];

    int tid = threadIdx.x;
    int lane = tid & 31, wid = tid >> 5;

    float vreg[K_];                       // column dual, register-resident
    float minv[K_];                       // absolute shortest-path dist
    #pragma unroll
    for (int k = 0; k < K_; k++) vreg[k] = 0.f;

    for (int j = tid; j < Q_; j += NT) p[j] = -1;
    if (tid == 0) u[T_] = 0.f;

    // ---- Phase 0: per-row argmin (greedy duals u[i] = row min, v = 0) ----
    for (int i = wid; i < T_; i += NW) {
        const float* row = cost + (size_t)i * Q_;
        unsigned long long best = ~0ull;
        for (int j = lane; j < Q_; j += 32) {
            unsigned long long key =
                ((unsigned long long)order_f(__ldg(row + j)) << 32) | (unsigned)j;
            if (key < best) best = key;
        }
        #pragma unroll
        for (int off = 16; off; off >>= 1) {
            unsigned long long oth = __shfl_xor_sync(0xFFFFFFFFu, best, off);
            if (oth < best) best = oth;
        }
        if (lane == 0) {
            argj[i] = (int)(best & 0xFFFFFFFFu);
            u[i] = unorder_f((unsigned)(best >> 32));
        }
    }
    __syncthreads();

    if (tid == 0) {
        for (int i = 0; i < T_; i++) {
            int j = argj[i];
            if (p[j] < 0) { p[j] = i; matched[i] = 1; }
            else matched[i] = 0;
        }
    }
    __syncthreads();

    // ---- Phase 1: shortest augmenting path for each unmatched row ----
    for (int i = 0; i < T_; i++) {
        if (matched[i]) continue;

        unsigned um = 0;                  // used bitmask for my K_ columns
        #pragma unroll
        for (int k = 0; k < K_; k++) {
            minv[k] = 1e30f;
            if (tid + k * NT >= Q_) um |= (1u << k);   // tail cols: never free
        }

        int j0 = Q_;                      // virtual start column
        int i0 = i;
        float shift = 0.f;                // dist(j0)
        int iter = 0;
        int j1;
        float Sf;

        while (true) {
            float base = shift - u[i0];
            const float* row = cost + (size_t)i0 * Q_;

            unsigned long long best = ~0ull;
            #pragma unroll
            for (int k = 0; k < K_; k++) {
                int j = tid + k * NT;
                if (!((um >> k) & 1u)) {
                    float cur = __ldg(row + j) - vreg[k] + base;
                    if (cur < minv[k]) { minv[k] = cur; sway[j] = j0; }
                    unsigned long long key =
                        ((unsigned long long)order_f(minv[k]) << 32) | (unsigned)j;
                    if (key < best) best = key;
                }
            }
            #pragma unroll
            for (int off = 16; off; off >>= 1) {
                unsigned long long oth = __shfl_xor_sync(0xFFFFFFFFu, best, off);
                if (oth < best) best = oth;
            }
            int buf = iter & 1;
            if (lane == 0) wred[buf][wid] = best;
            __syncthreads();

            unsigned long long tot = wred[buf][0];
            #pragma unroll
            for (int w = 1; w < NW; w++)
                if (wred[buf][w] < tot) tot = wred[buf][w];
            j1 = (int)(tot & 0xFFFFFFFFu);
            Sf = unorder_f((unsigned)(tot >> 32));

            int i0n = p[j1];
            if (i0n < 0) break;           // free column -> augment

            if ((j1 % NT) == tid) um |= (1u << (j1 / NT));
            j0 = j1;
            i0 = i0n;
            shift = Sf;
            iter++;
        }

        // deferred dual updates (sum of all in-loop delta updates)
        #pragma unroll
        for (int k = 0; k < K_; k++) {
            int j = tid + k * NT;
            if (j < Q_ && ((um >> k) & 1u)) {
                float diff = Sf - minv[k];   // S_final - dist(j)
                vreg[k] -= diff;
                u[p[j]] += diff;             // rows distinct across used cols
            }
        }
        if (tid == 0) u[i] += Sf;
        __syncthreads();                     // duals read p before augment writes

        if (tid == 0) {
            int j = j1;
            while (j != Q_) {
                int jn = sway[j];
                p[j] = (jn == Q_) ? i : p[jn];
                j = jn;
            }
        }
        __syncthreads();
    }

    // col[t] = matched query; write indices sorted by query (rank via count)
    for (int j = tid; j < Q_; j += NT) {
        int r = p[j];
        if (r >= 0) colarr[r] = j;
    }
    __syncthreads();

    if (writeIdx) {
        float* oidx = out + (size_t)B_ * Q_ * T_;
        for (int t = tid; t < T_; t += NT) {
            int c = colarr[t];
            int rank = 0;
            for (int s = 0; s < T_; s++) rank += (colarr[s] < c);
            oidx[(size_t)b * T_ + rank] = (float)c;                    // pred_idx
            oidx[(size_t)B_ * T_ + (size_t)b * T_ + rank] = (float)t;  // tgt_idx
        }
    }
}

// ---------------------------------------------------------------------------
extern "C" void kernel_launch(void* const* d_in, const int* in_sizes, int n_in,
                              void* d_out, int out_size) {
    const float* logits = (const float*)d_in[0];
    const float* pboxes = (const float*)d_in[1];
    const int*   labels = (const int*)d_in[2];
    const float* tboxes = (const float*)d_in[3];
    float* out = (float*)d_out;

    dim3 tg((Q_ + 31) / 32, B_);
    cost_fused_kernel<<<tg, NT>>>(logits, pboxes, labels, tboxes, out);

    int writeIdx = (out_size >= (int)((long long)B_ * Q_ * T_ + 2LL * B_ * T_)) ? 1 : 0;
    hungarian_kernel<<<B_, NT>>>(out, writeIdx);
}

// round 4
// speedup vs baseline: 3.0031x; 1.0146x over previous
#include <cuda_runtime.h>
#include <cstdint>

#define B_ 64
#define Q_ 900
#define T_ 100
#define C_ 256
#define NT 256
#define K_ 4            // columns per thread: NT*K_ >= Q_
#define NW (NT / 32)

// Scratch: transposed cost [B, T, Q] so hungarian reads contiguous rows.
__device__ float g_costT[(size_t)B_ * T_ * Q_];
// Per-(b,t) packed row-min: (order(cost) << 32) | q
__device__ unsigned long long g_rowmin[B_ * T_];

__device__ __forceinline__ unsigned order_f(float f) {
    unsigned o = __float_as_uint(f);
    return (o & 0x80000000u) ? ~o : (o | 0x80000000u);
}
__device__ __forceinline__ float unorder_f(unsigned o) {
    return __uint_as_float((o & 0x80000000u) ? (o ^ 0x80000000u) : ~o);
}

// ---------------------------------------------------------------------------
__global__ void init_rowmin_kernel() {
    int i = blockIdx.x * blockDim.x + threadIdx.x;
    if (i < B_ * T_) g_rowmin[i] = ~0ull;
}

// ---------------------------------------------------------------------------
// Kernel 1: one block per (b, 32-query tile). Computes cost for all T targets,
// writes out[B,Q,T] + g_costT[B,T,Q] (coalesced via smem tile), and folds the
// per-target row-min into g_rowmin with one atomicMin per (block, t).
// ---------------------------------------------------------------------------
__global__ void __launch_bounds__(NT) cost_fused_kernel(
        const float* __restrict__ logits,
        const float* __restrict__ pboxes,
        const int* __restrict__ labels,
        const float* __restrict__ tboxes,
        float* __restrict__ out) {
    __shared__ int   lab_s[T_];
    __shared__ float4 tb_s[T_];
    __shared__ float4 pb_s[32];
    __shared__ float tile[32][101];   // [q_in_tile][t]

    int b = blockIdx.y;
    int q0 = blockIdx.x * 32;
    int tid = threadIdx.x;

    if (tid < T_) {
        lab_s[tid] = labels[b * T_ + tid];
        tb_s[tid] = __ldg(&((const float4*)tboxes)[b * T_ + tid]);
    }
    if (tid < 32 && q0 + tid < Q_)
        pb_s[tid] = __ldg(&((const float4*)pboxes)[b * Q_ + q0 + tid]);
    __syncthreads();

    int qq = tid >> 3;                 // 0..31
    int q = q0 + qq;
    int t_lo = tid & 7;                // 0..7
    if (q < Q_) {
        float4 pb = pb_s[qq];
        float ax0 = pb.x - 0.5f * pb.z, ay0 = pb.y - 0.5f * pb.w;
        float ax1 = pb.x + 0.5f * pb.z, ay1 = pb.y + 0.5f * pb.w;
        float areaA = (ax1 - ax0) * (ay1 - ay0);
        const float* lrow = logits + ((long long)b * Q_ + q) * C_;
        float* orow = out + ((size_t)b * Q_ + q) * T_;

        #pragma unroll
        for (int s = 0; s < 13; s++) {
            int tt = t_lo + (s << 3);
            if (tt >= T_) break;

            float cc = -__ldg(lrow + lab_s[tt]);
            float4 tb = tb_s[tt];

            float cb = fabsf(pb.x - tb.x) + fabsf(pb.y - tb.y);
            cb += fabsf(pb.z - tb.z);
            cb += fabsf(pb.w - tb.w);

            float bx0 = tb.x - 0.5f * tb.z, by0 = tb.y - 0.5f * tb.w;
            float bx1 = tb.x + 0.5f * tb.z, by1 = tb.y + 0.5f * tb.w;

            float areaB = (bx1 - bx0) * (by1 - by0);
            float wx = fminf(ax1, bx1) - fmaxf(ax0, bx0); wx = fmaxf(wx, 0.f);
            float wy = fminf(ay1, by1) - fmaxf(ay0, by0); wy = fmaxf(wy, 0.f);
            float inter = wx * wy;
            float uni = areaA + areaB - inter;
            float iou = inter / uni;
            float ex = fmaxf(ax1, bx1) - fminf(ax0, bx0); ex = fmaxf(ex, 0.f);
            float ey = fmaxf(ay1, by1) - fminf(ay0, by0); ey = fmaxf(ey, 0.f);
            float enc = ex * ey;
            float giou = iou - (enc - uni) / enc;

            float val = (cc + cb) - giou;
            tile[qq][tt] = val;
            orow[tt] = val;                 // full 32B sectors per warp
        }
    }
    __syncthreads();

    // transposed copy (coalesced along q)
    for (int idx = tid; idx < 32 * T_; idx += NT) {
        int tt = idx >> 5, q2 = q0 + (idx & 31);
        if (q2 < Q_)
            g_costT[((size_t)b * T_ + tt) * Q_ + q2] = tile[idx & 31][tt];
    }

    // per-target min over this block's 32 queries -> global atomicMin
    if (tid < T_) {
        unsigned long long best = ~0ull;
        int qmax = min(32, Q_ - q0);
        for (int k = 0; k < qmax; k++) {
            unsigned long long key =
                ((unsigned long long)order_f(tile[k][tid]) << 32) | (unsigned)(q0 + k);
            if (key < best) best = key;
        }
        atomicMin(&g_rowmin[b * T_ + tid], best);
    }
}

// ---------------------------------------------------------------------------
// Kernel 2: JV, greedy init from precomputed row-mins + deferred-dual SAP.
// One CTA per batch.
// ---------------------------------------------------------------------------
__global__ void __launch_bounds__(NT) hungarian_kernel(float* __restrict__ out,
                                                       int writeIdx) {
    int b = blockIdx.x;
    const float* cost = g_costT + (size_t)b * T_ * Q_;

    __shared__ float u[T_ + 1];
    __shared__ int p[Q_];                 // row matched to col j (-1 free)
    __shared__ int sway[Q_];              // predecessor column
    __shared__ unsigned long long wred[2][NW];
    __shared__ int colarr[T_];
    __shared__ int argj[T_];
    __shared__ int matched[T_];

    int tid = threadIdx.x;
    int lane = tid & 31, wid = tid >> 5;

    float vreg[K_];
    float minv[K_];
    #pragma unroll
    for (int k = 0; k < K_; k++) vreg[k] = 0.f;

    for (int j = tid; j < Q_; j += NT) p[j] = -1;
    if (tid == 0) u[T_] = 0.f;

    // ---- Phase 0: greedy duals from precomputed row-mins ----
    if (tid < T_) {
        unsigned long long key = g_rowmin[b * T_ + tid];
        argj[tid] = (int)(key & 0xFFFFFFFFu);
        u[tid] = unorder_f((unsigned)(key >> 32));
    }
    __syncthreads();

    if (tid == 0) {
        for (int i = 0; i < T_; i++) {
            int j = argj[i];
            if (p[j] < 0) { p[j] = i; matched[i] = 1; }
            else matched[i] = 0;
        }
    }
    __syncthreads();

    // ---- Phase 1: shortest augmenting path for each unmatched row ----
    for (int i = 0; i < T_; i++) {
        if (matched[i]) continue;

        unsigned um = 0;
        #pragma unroll
        for (int k = 0; k < K_; k++) {
            minv[k] = 1e30f;
            if (tid + k * NT >= Q_) um |= (1u << k);
        }

        int j0 = Q_;
        int i0 = i;
        float shift = 0.f;
        int iter = 0;
        int j1;
        float Sf;

        while (true) {
            float base = shift - u[i0];
            const float* row = cost + (size_t)i0 * Q_;

            unsigned long long best = ~0ull;
            #pragma unroll
            for (int k = 0; k < K_; k++) {
                int j = tid + k * NT;
                if (!((um >> k) & 1u)) {
                    float cur = __ldg(row + j) - vreg[k] + base;
                    if (cur < minv[k]) { minv[k] = cur; sway[j] = j0; }
                    unsigned long long key =
                        ((unsigned long long)order_f(minv[k]) << 32) | (unsigned)j;
                    if (key < best) best = key;
                }
            }
            #pragma unroll
            for (int off = 16; off; off >>= 1) {
                unsigned long long oth = __shfl_xor_sync(0xFFFFFFFFu, best, off);
                if (oth < best) best = oth;
            }
            int buf = iter & 1;
            if (lane == 0) wred[buf][wid] = best;
            __syncthreads();

            unsigned long long tot = wred[buf][0];
            #pragma unroll
            for (int w = 1; w < NW; w++)
                if (wred[buf][w] < tot) tot = wred[buf][w];
            j1 = (int)(tot & 0xFFFFFFFFu);
            Sf = unorder_f((unsigned)(tot >> 32));

            int i0n = p[j1];
            if (i0n < 0) break;

            if ((j1 % NT) == tid) um |= (1u << (j1 / NT));
            j0 = j1;
            i0 = i0n;
            shift = Sf;
            iter++;
        }

        // deferred dual updates
        #pragma unroll
        for (int k = 0; k < K_; k++) {
            int j = tid + k * NT;
            if (j < Q_ && ((um >> k) & 1u)) {
                float diff = Sf - minv[k];
                vreg[k] -= diff;
                u[p[j]] += diff;
            }
        }
        if (tid == 0) u[i] += Sf;
        __syncthreads();

        if (tid == 0) {
            int j = j1;
            while (j != Q_) {
                int jn = sway[j];
                p[j] = (jn == Q_) ? i : p[jn];
                j = jn;
            }
        }
        __syncthreads();
    }

    // write indices sorted by query (rank via counting)
    for (int j = tid; j < Q_; j += NT) {
        int r = p[j];
        if (r >= 0) colarr[r] = j;
    }
    __syncthreads();

    if (writeIdx) {
        float* oidx = out + (size_t)B_ * Q_ * T_;
        for (int t = tid; t < T_; t += NT) {
            int c = colarr[t];
            int rank = 0;
            for (int s = 0; s < T_; s++) rank += (colarr[s] < c);
            oidx[(size_t)b * T_ + rank] = (float)c;                    // pred_idx
            oidx[(size_t)B_ * T_ + (size_t)b * T_ + rank] = (float)t;  // tgt_idx
        }
    }
}

// ---------------------------------------------------------------------------
extern "C" void kernel_launch(void* const* d_in, const int* in_sizes, int n_in,
                              void* d_out, int out_size) {
    const float* logits = (const float*)d_in[0];
    const float* pboxes = (const float*)d_in[1];
    const int*   labels = (const int*)d_in[2];
    const float* tboxes = (const float*)d_in[3];
    float* out = (float*)d_out;

    init_rowmin_kernel<<<(B_ * T_ + 255) / 256, 256>>>();

    dim3 tg((Q_ + 31) / 32, B_);
    cost_fused_kernel<<<tg, NT>>>(logits, pboxes, labels, tboxes, out);

    int writeIdx = (out_size >= (int)((long long)B_ * Q_ * T_ + 2LL * B_ * T_)) ? 1 : 0;
    hungarian_kernel<<<B_, NT>>>(out, writeIdx);
}